// round 16
// baseline (speedup 1.0000x reference)
#include <cuda_runtime.h>
#include <cuda_bf16.h>
#include <math.h>
#include <stdint.h>

// ---------------- problem constants ----------------
#define BSZ   8
#define NPT   32
#define NEDGE 1024
#define NPAIR 528
#define NECOL 640
#define LATC  1536

// ---------------- gemm smem layout (u32 words) ----------------
#define A_WORDS (128 * 20)
#define B_WORDS (16 * 136)
#define BUF_WORDS (2 * A_WORDS + 2 * B_WORDS)
#define AH_O 0
#define AL_O A_WORDS
#define BH_O (2 * A_WORDS)
#define BL_O (2 * A_WORDS + B_WORDS)
#define GEMM_SMEM_BYTES (2 * BUF_WORDS * 4)       // 75776 B

#define XC_HALF (BSZ * 1024 * NECOL)

// ---------------- scratch (__device__ globals) ----------------
__device__ float d_Gn[BSZ * 2048 * NPT];
__device__ float d_GnP[4 * BSZ * 2048 * NPT];
__device__ float d_XcP[2 * XC_HALF];
__device__ float d_Y [BSZ * 1024 * NEDGE];
__device__ float d_gateP[4 * BSZ * NEDGE];
__device__ float d_prP [4 * BSZ * 64 * NEDGE];

// packed bf16 k-pair operands
__device__ __align__(16) uint32_t d_WIh[2 * 512 * 768];
__device__ __align__(16) uint32_t d_WIl[2 * 512 * 768];
__device__ __align__(16) uint32_t d_CWh[2 * 512 * 256];
__device__ __align__(16) uint32_t d_CWl[2 * 512 * 256];
__device__ __align__(16) uint32_t d_WNh[2048 * 768];
__device__ __align__(16) uint32_t d_WNl[2048 * 768];
__device__ __align__(16) uint32_t d_Eph[BSZ * 768 * NECOL];
__device__ __align__(16) uint32_t d_Epl[BSZ * 768 * NECOL];
__device__ __align__(16) uint32_t d_Fnh[768 * 256];
__device__ __align__(16) uint32_t d_Fnl[768 * 256];
__device__ __align__(16) uint32_t d_Xph[BSZ * 2 * 256 * 1024];
__device__ __align__(16) uint32_t d_Xpl[BSZ * 2 * 256 * 1024];

// ---------------- helpers ----------------
__device__ __forceinline__ void split_pair(float x, float y, uint32_t& hp, uint32_t& lp) {
    __nv_bfloat16 hx = __float2bfloat16_rn(x), hy = __float2bfloat16_rn(y);
    __nv_bfloat16 lx = __float2bfloat16_rn(x - __bfloat162float(hx));
    __nv_bfloat16 ly = __float2bfloat16_rn(y - __bfloat162float(hy));
    __nv_bfloat162 h2(hx, hy), l2(lx, ly);
    hp = *reinterpret_cast<uint32_t*>(&h2);
    lp = *reinterpret_cast<uint32_t*>(&l2);
}

__device__ __forceinline__ void mma16816(float* c, const uint32_t* a, const uint32_t* b) {
    asm volatile("mma.sync.aligned.m16n8k16.row.col.f32.bf16.bf16.f32 "
                 "{%0,%1,%2,%3}, {%4,%5,%6,%7}, {%8,%9}, {%0,%1,%2,%3};"
                 : "+f"(c[0]), "+f"(c[1]), "+f"(c[2]), "+f"(c[3])
                 : "r"(a[0]), "r"(a[1]), "r"(a[2]), "r"(a[3]),
                   "r"(b[0]), "r"(b[1]));
}

__device__ __forceinline__ void ldsm4(uint32_t* r, uint32_t addr) {
    asm volatile("ldmatrix.sync.aligned.m8n8.x4.shared.b16 {%0,%1,%2,%3}, [%4];"
                 : "=r"(r[0]), "=r"(r[1]), "=r"(r[2]), "=r"(r[3]) : "r"(addr));
}

__device__ __forceinline__ uint32_t smem_u32(const void* p) {
    uint32_t a;
    asm("{ .reg .u64 t; cvta.to.shared.u64 t, %1; cvt.u32.u64 %0, t; }" : "=r"(a) : "l"(p));
    return a;
}
__device__ __forceinline__ void cpa16(uint32_t dst_s, const void* src) {
    asm volatile("cp.async.cg.shared.global [%0], [%1], 16;" :: "r"(dst_s), "l"(src));
}

// pair index helpers
__device__ __forceinline__ int pair_index(int i, int j) {   // i <= j
    return 32 * i - ((i * (i - 1)) >> 1) + (j - i);
}
__device__ __forceinline__ void pair_decode(int pc, int& i, int& j) {
    float s = sqrtf(4225.0f - 8.0f * (float)pc);
    i = (int)((65.0f - s) * 0.5f);
    int base = 32 * i - ((i * (i - 1)) >> 1);
    if (pc < base) { i--; base = 32 * i - ((i * (i - 1)) >> 1); }
    else { int nxt = base + (32 - i); if (pc >= nxt) { i++; base = nxt; } }
    j = i + (pc - base);
}

// ---------------- K1: fused align + pack ----------------
#define QTOT 672
__global__ void alignPack(const float* __restrict__ f0, const float* __restrict__ f1,
                          const float* __restrict__ f2, const float* __restrict__ f3,
                          const float* __restrict__ f4, const float* __restrict__ f5,
                          const float* __restrict__ P)
{
    int idx = blockIdx.x * 256 + threadIdx.x;
    if (idx >= BSZ * 768 * QTOT) return;
    int q  = idx % QTOT;
    int t  = idx / QTOT;
    int k2 = t % 768;
    int b  = t / 768;

    if (q >= 32 + NPAIR) {
        size_t o = ((size_t)b * 768 + k2) * NECOL + (q - 32);
        d_Eph[o] = 0u; d_Epl[o] = 0u;
        return;
    }

    int pid = q;
    float px, py;
    if (pid < NPT) {
        px = P[(b * NPT + pid) * 2 + 0];
        py = P[(b * NPT + pid) * 2 + 1];
    } else {
        int i, j;
        pair_decode(pid - NPT, i, j);
        px = 0.5f * (P[(b * NPT + i) * 2 + 0] + P[(b * NPT + j) * 2 + 0]);
        py = 0.5f * (P[(b * NPT + i) * 2 + 1] + P[(b * NPT + j) * 2 + 1]);
    }

    int c = 2 * k2;
    const float* f; int choff, H, C;
    if      (c < 64)   { f = f0; choff = 0;    H = 128; C = 64;  }
    else if (c < 128)  { f = f1; choff = 64;   H = 64;  C = 64;  }
    else if (c < 256)  { f = f2; choff = 128;  H = 32;  C = 128; }
    else if (c < 512)  { f = f3; choff = 256;  H = 16;  C = 256; }
    else if (c < 1024) { f = f4; choff = 512;  H = 8;   C = 512; }
    else               { f = f5; choff = 1024; H = 1;   C = 512; }

    float xs = fminf(fmaxf(px * ((float)H * (1.0f / 256.0f)) - 0.5f, 0.0f), (float)(H - 1));
    float ys = fminf(fmaxf(py * ((float)H * (1.0f / 256.0f)) - 0.5f, 0.0f), (float)(H - 1));
    float x0f = floorf(xs), y0f = floorf(ys);
    float wx = xs - x0f, wy = ys - y0f;
    int x0 = (int)x0f, y0 = (int)y0f;
    int x1 = min(x0 + 1, H - 1), y1 = min(y0 + 1, H - 1);
    float w00 = (1.f - wx) * (1.f - wy);
    float w01 = wx * (1.f - wy);
    float w10 = (1.f - wx) * wy;
    float w11 = wx * wy;
    int i00 = y0 * H + x0, i01 = y0 * H + x1, i10 = y1 * H + x0, i11 = y1 * H + x1;

    const int hw = H * H;
    const float* b0 = f + (size_t)(b * C + (c - choff)) * hw;
    const float* b1 = b0 + hw;
    float v0 = b0[i00] * w00 + b0[i01] * w01 + b0[i10] * w10 + b0[i11] * w11;
    float v1 = b1[i00] * w00 + b1[i01] * w01 + b1[i10] * w10 + b1[i11] * w11;

    uint32_t hp, lp;
    split_pair(v0, v1, hp, lp);
    if (pid < NPT) {
        int o = k2 * 256 + b * NPT + pid;
        d_Fnh[o] = hp; d_Fnl[o] = lp;
    } else {
        size_t o = ((size_t)b * 768 + k2) * NECOL + (pid - NPT);
        d_Eph[o] = hp; d_Epl[o] = lp;
    }
}

// ---------------- merged weight conversion ----------------
#define NWI (2 * 512 * 768)
#define NWC (2 * 512 * 256)
#define NWN (2048 * 768)
__global__ void convW(const float* __restrict__ g_iw, const float* __restrict__ p_iw,
                      const float* __restrict__ g_cw, const float* __restrict__ p_cw)
{
    int idx = blockIdx.x * 256 + threadIdx.x;
    if (idx < NWI) {
        int k2 = idx % 768;
        int r  = (idx / 768) & 511;
        int net = idx / (512 * 768);
        const float* w = (net ? p_iw : g_iw) + (size_t)r * 4608 + 3072 + 2 * k2;
        split_pair(w[0], w[1], d_WIh[idx], d_WIl[idx]);
    } else if (idx < NWI + NWC) {
        int q = idx - NWI;
        int k2 = q & 255;
        int r  = (q >> 8) & 511;
        int net = q >> 17;
        const float* w = (net ? p_cw : g_cw) + (size_t)r * 512 + 2 * k2;
        split_pair(w[0], w[1], d_CWh[q], d_CWl[q]);
    } else if (idx < NWI + NWC + NWN) {
        int q = idx - NWI - NWC;
        int k2 = q % 768;
        int r  = q / 768;
        int part = r >> 9;
        const float* w = (part >= 2 ? p_iw : g_iw) + (size_t)(r & 511) * 4608
                         + ((part & 1) ? 1536 : 0) + 2 * k2;
        split_pair(w[0], w[1], d_WNh[q], d_WNl[q]);
    }
}

// ---------------- convX: XcP halves + Gn -> BN/ReLU packed chorus operand ----------------
__global__ void convX(const float* __restrict__ g_bg, const float* __restrict__ g_bb,
                      const float* __restrict__ g_bm, const float* __restrict__ g_bv,
                      const float* __restrict__ p_bg, const float* __restrict__ p_bb,
                      const float* __restrict__ p_bm, const float* __restrict__ p_bv)
{
    int idx = blockIdx.x * 256 + threadIdx.x;       // 8*2*256*1024
    int n  = idx & 1023;
    int t  = idx >> 10;
    int k2 = t & 255;
    int z  = t >> 8;
    int b = z >> 1, net = z & 1;
    int k = 2 * k2;

    int i = n >> 5, j = n & 31;
    int ii = min(i, j), jj = max(i, j);
    int c = pair_index(ii, jj);

    size_t crow = ((size_t)b * 1024 + net * 512 + k) * NECOL + c;
    float v0 = d_XcP[crow] + d_XcP[XC_HALF + crow];
    float v1 = d_XcP[crow + NECOL] + d_XcP[XC_HALF + crow + NECOL];

    size_t gi = ((size_t)b * 2048 + net * 1024 + k) * NPT;
    size_t gj = gi + (size_t)512 * NPT;
    float x0 = v0 + d_Gn[gi + i] + d_Gn[gj + j];
    float x1 = v1 + d_Gn[gi + NPT + i] + d_Gn[gj + NPT + j];

    const float* BG = net ? p_bg : g_bg;
    const float* BB = net ? p_bb : g_bb;
    const float* BM = net ? p_bm : g_bm;
    const float* BV = net ? p_bv : g_bv;
    float sc0 = BG[k] * rsqrtf(BV[k] + 1e-5f);
    float sh0 = BB[k] - BM[k] * sc0;
    float sc1 = BG[k + 1] * rsqrtf(BV[k + 1] + 1e-5f);
    float sh1 = BB[k + 1] - BM[k + 1] * sc1;
    float y0 = fmaxf(x0 * sc0 + sh0, 0.f);
    float y1 = fmaxf(x1 * sc1 + sh1, 0.f);
    split_pair(y0, y1, d_Xph[idx], d_Xpl[idx]);
}

// ---------------- HMMA GEMM ----------------
// MODE 0 (intro): compact store to d_XcP; K-split 2 via blockIdx.y LSB
// MODE 1 (chorus): Y = D + (XcP+Gi+Gj) + cb  (residual reconstructed in epilogue)
// MODE 2 (node):   GnP partials (k-split 4 via blockIdx.z)
template<int K2TOT, int NTOT, int MODE>
__global__ void __launch_bounds__(256, 2) gemm_mma(
    const uint32_t* __restrict__ Ah_g, const uint32_t* __restrict__ Al_g,
    const uint32_t* __restrict__ Bh_g, const uint32_t* __restrict__ Bl_g,
    const float* __restrict__ g_cb, const float* __restrict__ p_cb)
{
    extern __shared__ uint32_t smw[];
    const uint32_t sbase = smem_u32(smw);

    const int tid  = threadIdx.x;
    const int lane = tid & 31, wid = tid >> 5;
    const int wm = wid >> 2, wn = wid & 3;
    const int b    = blockIdx.z;
    const int half = (MODE == 0) ? (blockIdx.y & 1) : 0;
    const int row0 = (MODE == 0) ? (blockIdx.y >> 1) * 128 : blockIdx.y * 128;
    const int col0 = blockIdx.x * 128;
    const int net  = (row0 >> 9) & 1;

    const uint32_t* Ah = Ah_g + (size_t)row0 * K2TOT;
    const uint32_t* Al = Al_g + (size_t)row0 * K2TOT;
    const int bz = (MODE == 0) ? b : (MODE == 1 ? b * 2 + net : 0);
    const uint32_t* Bh = Bh_g + (size_t)bz * K2TOT * NTOT + col0;
    const uint32_t* Bl = Bl_g + (size_t)bz * K2TOT * NTOT + col0;

    constexpr int NCH = K2TOT / 16;
    constexpr int CHUNKS = (MODE == 2) ? NCH / 4 : (MODE == 0 ? NCH / 2 : NCH);
    const int kc0 = (MODE == 2) ? blockIdx.z * CHUNKS : (MODE == 0 ? half * CHUNKS : 0);

    const int lrow = lane & 15;
    const int lcolw = (lane >> 4) * 4;

    #define PREFETCH(kc, bufw) do { \
        _Pragma("unroll") \
        for (int i = 0; i < 2; i++) { \
            int t = tid + i * 256; \
            int row = t >> 2, seg = t & 3; \
            size_t go = (size_t)row * K2TOT + (kc) * 16 + seg * 4; \
            cpa16(sbase + ((bufw) + AH_O + row * 20 + seg * 4) * 4, Ah + go); \
            cpa16(sbase + ((bufw) + AL_O + row * 20 + seg * 4) * 4, Al + go); \
            int brow = t >> 5, bseg = t & 31; \
            size_t gb = (size_t)((kc) * 16 + brow) * NTOT + bseg * 4; \
            cpa16(sbase + ((bufw) + BH_O + brow * 136 + bseg * 4) * 4, Bh + gb); \
            cpa16(sbase + ((bufw) + BL_O + brow * 136 + bseg * 4) * 4, Bl + gb); \
        } \
        asm volatile("cp.async.commit_group;" ::: "memory"); \
    } while (0)

    float acc[4][4][4];
    #pragma unroll
    for (int i = 0; i < 4; i++)
        #pragma unroll
        for (int j = 0; j < 4; j++)
            #pragma unroll
            for (int v = 0; v < 4; v++) acc[i][j][v] = 0.f;

    PREFETCH(kc0, 0);

    #pragma unroll 1
    for (int ci = 0; ci < CHUNKS; ci++) {
        const int bufw = (ci & 1) * BUF_WORDS;
        if (ci + 1 < CHUNKS) {
            PREFETCH(kc0 + ci + 1, ((ci + 1) & 1) * BUF_WORDS);
            asm volatile("cp.async.wait_group 1;" ::: "memory");
        } else {
            asm volatile("cp.async.wait_group 0;" ::: "memory");
        }
        __syncthreads();

        const uint32_t* BhS = smw + bufw + BH_O;
        const uint32_t* BlS = smw + bufw + BL_O;

        #pragma unroll
        for (int s = 0; s < 2; s++) {
            const int k2a = s * 8 + (lane & 3);
            uint32_t bh[4][2], bl[4][2];
            #pragma unroll
            for (int nf = 0; nf < 4; nf++) {
                int n = wn * 32 + nf * 8 + (lane >> 2);
                bh[nf][0] = BhS[k2a * 136 + n];
                bh[nf][1] = BhS[(k2a + 4) * 136 + n];
                bl[nf][0] = BlS[k2a * 136 + n];
                bl[nf][1] = BlS[(k2a + 4) * 136 + n];
            }
            #pragma unroll
            for (int mf = 0; mf < 4; mf++) {
                uint32_t aaddr = sbase + (uint32_t)((ci & 1) * BUF_WORDS + AH_O
                                 + (wm * 64 + mf * 16 + lrow) * 20 + s * 8 + lcolw) * 4;
                uint32_t ah[4], al[4];
                ldsm4(ah, aaddr);
                ldsm4(al, aaddr + A_WORDS * 4);
                #pragma unroll
                for (int nf = 0; nf < 4; nf++) {
                    mma16816(acc[mf][nf], ah, bh[nf]);
                    mma16816(acc[mf][nf], ah, bl[nf]);
                    mma16816(acc[mf][nf], al, bh[nf]);
                }
            }
        }
        __syncthreads();
    }
    #undef PREFETCH

    // ---- epilogue ----
    #pragma unroll
    for (int mf = 0; mf < 4; mf++) {
        int row_g = row0 + wm * 64 + mf * 16 + (lane >> 2);
        #pragma unroll
        for (int nf = 0; nf < 4; nf++) {
            int colg = col0 + wn * 32 + nf * 8 + (lane & 3) * 2;
            float* a = acc[mf][nf];
            if (MODE == 2) {
                int bb = colg >> 5, p = colg & 31;
                float* dst = d_GnP + (((size_t)blockIdx.z * 8 + bb) * 2048) * NPT;
                *(float2*)&dst[(size_t)row_g * NPT + p] = make_float2(a[0], a[1]);
                *(float2*)&dst[(size_t)(row_g + 8) * NPT + p] = make_float2(a[2], a[3]);
            } else if (MODE == 0) {
                float* dst = d_XcP + (size_t)half * XC_HALF;
                size_t obase = ((size_t)b * 1024 + row_g) * NECOL;
                *(float2*)&dst[obase + colg] = make_float2(a[0], a[1]);
                *(float2*)&dst[obase + 8 * NECOL + colg] = make_float2(a[2], a[3]);
            } else {
                // chorus: reconstruct residual X = Xc + Gi + Gj from compact partials
                int r = row_g & 511;
                const float* CB = net ? p_cb : g_cb;
                float cb0 = CB[r], cb8 = CB[r + 8];

                int i  = colg >> 5;                    // same for colg and colg+1
                int j0 = colg & 31, j1 = j0 + 1;
                int c0 = pair_index(min(i, j0), max(i, j0));
                int c1 = pair_index(min(i, j1), max(i, j1));

                size_t crow0 = ((size_t)b * 1024 + row_g) * NECOL;
                size_t crow8 = crow0 + 8 * NECOL;
                size_t gi0 = ((size_t)b * 2048 + net * 1024 + r) * NPT;
                size_t gj0 = gi0 + (size_t)512 * NPT;

                float giA = d_Gn[gi0 + i];
                float giB = d_Gn[gi0 + 8 * NPT + i];
                float gjA0 = d_Gn[gj0 + j0], gjA1 = d_Gn[gj0 + j1];
                float gjB0 = d_Gn[gj0 + 8 * NPT + j0], gjB1 = d_Gn[gj0 + 8 * NPT + j1];

                float x00 = d_XcP[crow0 + c0] + d_XcP[XC_HALF + crow0 + c0] + giA + gjA0;
                float x01 = d_XcP[crow0 + c1] + d_XcP[XC_HALF + crow0 + c1] + giA + gjA1;
                float x80 = d_XcP[crow8 + c0] + d_XcP[XC_HALF + crow8 + c0] + giB + gjB0;
                float x81 = d_XcP[crow8 + c1] + d_XcP[XC_HALF + crow8 + c1] + giB + gjB1;

                size_t obase = ((size_t)b * 1024 + row_g) * NEDGE;
                float2 w0 = make_float2(a[0] + x00 + cb0, a[1] + x01 + cb0);
                float2 w1 = make_float2(a[2] + x80 + cb8, a[3] + x81 + cb8);
                *(float2*)&d_Y[obase + colg] = w0;
                *(float2*)&d_Y[obase + 8 * NEDGE + colg] = w1;
            }
        }
    }
}

// ---------------- reduce node partials + bias ----------------
__global__ void reduceGn(const float* __restrict__ g_ib, const float* __restrict__ p_ib)
{
    int idx = blockIdx.x * 256 + threadIdx.x;
    int r = (idx >> 5) & 2047;
    float bias = (r < 512) ? g_ib[r] : ((r >= 1024 && r < 1536) ? p_ib[r - 1024] : 0.f);
    float s = bias;
    #pragma unroll
    for (int z = 0; z < 4; z++)
        s += d_GnP[(size_t)z * (8 * 2048 * NPT) + idx];
    d_Gn[idx] = s;
}

// ---------------- outro ----------------
__global__ void __launch_bounds__(128) outro_kernel(const float* __restrict__ g_ow,
                                                    const float* __restrict__ p_ow)
{
    __shared__ float wg[128];
    __shared__ float wp[64 * 128];
    const int tx = threadIdx.x;
    const int m  = blockIdx.x * 128 + tx;
    const int b  = blockIdx.y;
    const int rz = blockIdx.z;
    const int r0 = rz * 128;

    wg[tx] = g_ow[r0 + tx];
    for (int i = tx; i < 64 * 128; i += 128) {
        int oc = i >> 7, r = i & 127;
        wp[i] = p_ow[(size_t)oc * 512 + r0 + r];
    }
    __syncthreads();

    float accg = 0.f;
    float acc[64];
    #pragma unroll
    for (int oc = 0; oc < 64; oc++) acc[oc] = 0.f;

    const float* Yg = d_Y + ((size_t)b * 1024 + r0) * NEDGE + m;
    const float* Yp = Yg + (size_t)512 * NEDGE;
    #pragma unroll 4
    for (int r = 0; r < 128; r++) {
        float yg = Yg[(size_t)r * NEDGE];
        float yp = Yp[(size_t)r * NEDGE];
        accg += wg[r] * yg;
        #pragma unroll
        for (int oc = 0; oc < 64; oc++)
            acc[oc] += wp[oc * 128 + r] * yp;
    }

    d_gateP[((size_t)rz * 8 + b) * NEDGE + m] = accg;
    float* dst = d_prP + ((size_t)rz * 8 + b) * 64 * NEDGE + m;
    #pragma unroll
    for (int oc = 0; oc < 64; oc++)
        dst[(size_t)oc * NEDGE] = acc[oc];
}

// ---------------- final ----------------
__global__ void final_kernel(const int* __restrict__ nvec,
                             const float* __restrict__ g_ob, const float* __restrict__ p_ob,
                             float* __restrict__ out)
{
    const int m = blockIdx.x * blockDim.x + threadIdx.x;
    const int b = blockIdx.y;
    if (m >= NEDGE) return;
    const int i = m >> 5, j = m & 31;
    const int nb = nvec[b];
    const bool ok = (i < nb) && (j < nb);

    float gsum = g_ob[0];
    #pragma unroll
    for (int z = 0; z < 4; z++)
        gsum += d_gateP[((size_t)z * 8 + b) * NEDGE + m];

    float pv[64];
    float ss = 0.f;
    #pragma unroll
    for (int c = 0; c < 64; c++) {
        float v = p_ob[c];
        #pragma unroll
        for (int z = 0; z < 4; z++)
            v += d_prP[(((size_t)z * 8 + b) * 64 + c) * NEDGE + m];
        pv[c] = v;
        ss += v * v;
    }
    float g = 1.f / (1.f + expf(-gsum));
    float s = ok ? (g / fmaxf(sqrtf(ss), 1e-12f)) : 0.f;

    #pragma unroll
    for (int c = 0; c < 64; c++)
        out[((size_t)b * 64 + c) * NEDGE + m] = pv[c] * s;
}

// ---------------- launch ----------------
extern "C" void kernel_launch(void* const* d_in, const int* in_sizes, int n_in,
                              void* d_out, int out_size)
{
    const float* f0 = (const float*)d_in[0];
    const float* f1 = (const float*)d_in[1];
    const float* f2 = (const float*)d_in[2];
    const float* f3 = (const float*)d_in[3];
    const float* f4 = (const float*)d_in[4];
    const float* f5 = (const float*)d_in[5];
    const float* P  = (const float*)d_in[6];
    const int*   nv = (const int*)d_in[7];
    const float* g_iw = (const float*)d_in[8];
    const float* g_ib = (const float*)d_in[9];
    const float* g_bg = (const float*)d_in[10];
    const float* g_bb = (const float*)d_in[11];
    const float* g_bm = (const float*)d_in[12];
    const float* g_bv = (const float*)d_in[13];
    const float* g_cw = (const float*)d_in[14];
    const float* g_cb = (const float*)d_in[15];
    const float* g_ow = (const float*)d_in[16];
    const float* g_ob = (const float*)d_in[17];
    const float* p_iw = (const float*)d_in[18];
    const float* p_ib = (const float*)d_in[19];
    const float* p_bg = (const float*)d_in[20];
    const float* p_bb = (const float*)d_in[21];
    const float* p_bm = (const float*)d_in[22];
    const float* p_bv = (const float*)d_in[23];
    const float* p_cw = (const float*)d_in[24];
    const float* p_cb = (const float*)d_in[25];
    const float* p_ow = (const float*)d_in[26];
    const float* p_ob = (const float*)d_in[27];
    float* out = (float*)d_out;

    cudaFuncSetAttribute(gemm_mma<768, NECOL, 0>, cudaFuncAttributeMaxDynamicSharedMemorySize, GEMM_SMEM_BYTES);
    cudaFuncSetAttribute(gemm_mma<256, 1024, 1>,  cudaFuncAttributeMaxDynamicSharedMemorySize, GEMM_SMEM_BYTES);
    cudaFuncSetAttribute(gemm_mma<768, 256, 2>,   cudaFuncAttributeMaxDynamicSharedMemorySize, GEMM_SMEM_BYTES);

    uint32_t *pWIh, *pWIl, *pCWh, *pCWl, *pWNh, *pWNl, *pEph, *pEpl, *pFnh, *pFnl, *pXph, *pXpl;
    cudaGetSymbolAddress((void**)&pWIh, d_WIh);
    cudaGetSymbolAddress((void**)&pWIl, d_WIl);
    cudaGetSymbolAddress((void**)&pCWh, d_CWh);
    cudaGetSymbolAddress((void**)&pCWl, d_CWl);
    cudaGetSymbolAddress((void**)&pWNh, d_WNh);
    cudaGetSymbolAddress((void**)&pWNl, d_WNl);
    cudaGetSymbolAddress((void**)&pEph, d_Eph);
    cudaGetSymbolAddress((void**)&pEpl, d_Epl);
    cudaGetSymbolAddress((void**)&pFnh, d_Fnh);
    cudaGetSymbolAddress((void**)&pFnl, d_Fnl);
    cudaGetSymbolAddress((void**)&pXph, d_Xph);
    cudaGetSymbolAddress((void**)&pXpl, d_Xpl);

    alignPack<<<(BSZ * 768 * QTOT + 255) / 256, 256>>>(f0, f1, f2, f3, f4, f5, P);
    convW<<<(NWI + NWC + NWN + 255) / 256, 256>>>(g_iw, p_iw, g_cw, p_cw);

    gemm_mma<768, NECOL, 0><<<dim3(5, 16, BSZ), 256, GEMM_SMEM_BYTES>>>(
        pWIh, pWIl, pEph, pEpl, nullptr, nullptr);

    gemm_mma<768, 256, 2><<<dim3(2, 16, 4), 256, GEMM_SMEM_BYTES>>>(
        pWNh, pWNl, pFnh, pFnl, nullptr, nullptr);
    reduceGn<<<(BSZ * 2048 * NPT) / 256, 256>>>(g_ib, p_ib);

    convX<<<(BSZ * 2 * 256 * 1024) / 256, 256>>>(g_bg, g_bb, g_bm, g_bv,
                                                 p_bg, p_bb, p_bm, p_bv);

    gemm_mma<256, 1024, 1><<<dim3(8, 8, BSZ), 256, GEMM_SMEM_BYTES>>>(
        pCWh, pCWl, pXph, pXpl, g_cb, p_cb);

    outro_kernel<<<dim3(8, BSZ, 4), 128>>>(g_ow, p_ow);
    final_kernel<<<dim3(4, BSZ), 256>>>(nv, g_ob, p_ob, out);
}

// round 17
// speedup vs baseline: 1.5942x; 1.5942x over previous
#include <cuda_runtime.h>
#include <cuda_bf16.h>
#include <math.h>
#include <stdint.h>

// ---------------- problem constants ----------------
#define BSZ   8
#define NPT   32
#define NEDGE 1024
#define NPAIR 528
#define NECOL 640
#define LATC  1536

// ---------------- gemm smem layout (u32 words) ----------------
#define A_WORDS (128 * 20)
#define B_WORDS (16 * 136)
#define BUF_WORDS (2 * A_WORDS + 2 * B_WORDS)
#define AH_O 0
#define AL_O A_WORDS
#define BH_O (2 * A_WORDS)
#define BL_O (2 * A_WORDS + B_WORDS)
#define GEMM_SMEM_BYTES (2 * BUF_WORDS * 4)       // 75776 B

#define XC_HALF (BSZ * 1024 * NECOL)

// ---------------- scratch (__device__ globals) ----------------
__device__ float d_Gn[BSZ * 2048 * NPT];
__device__ float d_GnP[4 * BSZ * 2048 * NPT];
__device__ float d_XcP[2 * XC_HALF];
__device__ float d_X [BSZ * 1024 * NEDGE];
__device__ float d_Y [BSZ * 1024 * NEDGE];
__device__ float d_gateP[4 * BSZ * NEDGE];
__device__ float d_prP [4 * BSZ * 64 * NEDGE];

// packed bf16 k-pair operands
__device__ __align__(16) uint32_t d_WIh[2 * 512 * 768];
__device__ __align__(16) uint32_t d_WIl[2 * 512 * 768];
__device__ __align__(16) uint32_t d_CWh[2 * 512 * 256];
__device__ __align__(16) uint32_t d_CWl[2 * 512 * 256];
__device__ __align__(16) uint32_t d_WNh[2048 * 768];
__device__ __align__(16) uint32_t d_WNl[2048 * 768];
__device__ __align__(16) uint32_t d_Eph[BSZ * 768 * NECOL];
__device__ __align__(16) uint32_t d_Epl[BSZ * 768 * NECOL];
__device__ __align__(16) uint32_t d_Fnh[768 * 256];
__device__ __align__(16) uint32_t d_Fnl[768 * 256];
__device__ __align__(16) uint32_t d_Xph[BSZ * 2 * 256 * 1024];
__device__ __align__(16) uint32_t d_Xpl[BSZ * 2 * 256 * 1024];

// ---------------- helpers ----------------
__device__ __forceinline__ void split_pair(float x, float y, uint32_t& hp, uint32_t& lp) {
    __nv_bfloat16 hx = __float2bfloat16_rn(x), hy = __float2bfloat16_rn(y);
    __nv_bfloat16 lx = __float2bfloat16_rn(x - __bfloat162float(hx));
    __nv_bfloat16 ly = __float2bfloat16_rn(y - __bfloat162float(hy));
    __nv_bfloat162 h2(hx, hy), l2(lx, ly);
    hp = *reinterpret_cast<uint32_t*>(&h2);
    lp = *reinterpret_cast<uint32_t*>(&l2);
}

__device__ __forceinline__ void mma16816(float* c, const uint32_t* a, const uint32_t* b) {
    asm volatile("mma.sync.aligned.m16n8k16.row.col.f32.bf16.bf16.f32 "
                 "{%0,%1,%2,%3}, {%4,%5,%6,%7}, {%8,%9}, {%0,%1,%2,%3};"
                 : "+f"(c[0]), "+f"(c[1]), "+f"(c[2]), "+f"(c[3])
                 : "r"(a[0]), "r"(a[1]), "r"(a[2]), "r"(a[3]),
                   "r"(b[0]), "r"(b[1]));
}

__device__ __forceinline__ void ldsm4(uint32_t* r, uint32_t addr) {
    asm volatile("ldmatrix.sync.aligned.m8n8.x4.shared.b16 {%0,%1,%2,%3}, [%4];"
                 : "=r"(r[0]), "=r"(r[1]), "=r"(r[2]), "=r"(r[3]) : "r"(addr));
}

__device__ __forceinline__ uint32_t smem_u32(const void* p) {
    uint32_t a;
    asm("{ .reg .u64 t; cvta.to.shared.u64 t, %1; cvt.u32.u64 %0, t; }" : "=r"(a) : "l"(p));
    return a;
}
__device__ __forceinline__ void cpa16(uint32_t dst_s, const void* src) {
    asm volatile("cp.async.cg.shared.global [%0], [%1], 16;" :: "r"(dst_s), "l"(src));
}

// pair index helpers
__device__ __forceinline__ int pair_index(int i, int j) {   // i <= j
    return 32 * i - ((i * (i - 1)) >> 1) + (j - i);
}
__device__ __forceinline__ void pair_decode(int pc, int& i, int& j) {
    float s = sqrtf(4225.0f - 8.0f * (float)pc);
    i = (int)((65.0f - s) * 0.5f);
    int base = 32 * i - ((i * (i - 1)) >> 1);
    if (pc < base) { i--; base = 32 * i - ((i * (i - 1)) >> 1); }
    else { int nxt = base + (32 - i); if (pc >= nxt) { i++; base = nxt; } }
    j = i + (pc - base);
}

// ---------------- K1: fused align + pack (channel pairs -> bf16 hi/lo operands) ----------------
#define QTOT 672
__global__ void alignPack(const float* __restrict__ f0, const float* __restrict__ f1,
                          const float* __restrict__ f2, const float* __restrict__ f3,
                          const float* __restrict__ f4, const float* __restrict__ f5,
                          const float* __restrict__ P)
{
    int idx = blockIdx.x * 256 + threadIdx.x;
    if (idx >= BSZ * 768 * QTOT) return;
    int q  = idx % QTOT;
    int t  = idx / QTOT;
    int k2 = t % 768;
    int b  = t / 768;

    if (q >= 32 + NPAIR) {                 // zero-fill padded E cols 528..639
        size_t o = ((size_t)b * 768 + k2) * NECOL + (q - 32);
        d_Eph[o] = 0u; d_Epl[o] = 0u;
        return;
    }

    int pid = q;
    float px, py;
    if (pid < NPT) {
        px = P[(b * NPT + pid) * 2 + 0];
        py = P[(b * NPT + pid) * 2 + 1];
    } else {
        int i, j;
        pair_decode(pid - NPT, i, j);
        px = 0.5f * (P[(b * NPT + i) * 2 + 0] + P[(b * NPT + j) * 2 + 0]);
        py = 0.5f * (P[(b * NPT + i) * 2 + 1] + P[(b * NPT + j) * 2 + 1]);
    }

    int c = 2 * k2;                        // channel pair (c, c+1), never straddles levels
    const float* f; int choff, H, C;
    if      (c < 64)   { f = f0; choff = 0;    H = 128; C = 64;  }
    else if (c < 128)  { f = f1; choff = 64;   H = 64;  C = 64;  }
    else if (c < 256)  { f = f2; choff = 128;  H = 32;  C = 128; }
    else if (c < 512)  { f = f3; choff = 256;  H = 16;  C = 256; }
    else if (c < 1024) { f = f4; choff = 512;  H = 8;   C = 512; }
    else               { f = f5; choff = 1024; H = 1;   C = 512; }

    float xs = fminf(fmaxf(px * ((float)H * (1.0f / 256.0f)) - 0.5f, 0.0f), (float)(H - 1));
    float ys = fminf(fmaxf(py * ((float)H * (1.0f / 256.0f)) - 0.5f, 0.0f), (float)(H - 1));
    float x0f = floorf(xs), y0f = floorf(ys);
    float wx = xs - x0f, wy = ys - y0f;
    int x0 = (int)x0f, y0 = (int)y0f;
    int x1 = min(x0 + 1, H - 1), y1 = min(y0 + 1, H - 1);
    float w00 = (1.f - wx) * (1.f - wy);
    float w01 = wx * (1.f - wy);
    float w10 = (1.f - wx) * wy;
    float w11 = wx * wy;
    int i00 = y0 * H + x0, i01 = y0 * H + x1, i10 = y1 * H + x0, i11 = y1 * H + x1;

    const int hw = H * H;
    const float* b0 = f + (size_t)(b * C + (c - choff)) * hw;
    const float* b1 = b0 + hw;
    float v0 = b0[i00] * w00 + b0[i01] * w01 + b0[i10] * w10 + b0[i11] * w11;
    float v1 = b1[i00] * w00 + b1[i01] * w01 + b1[i10] * w10 + b1[i11] * w11;

    uint32_t hp, lp;
    split_pair(v0, v1, hp, lp);
    if (pid < NPT) {
        int o = k2 * 256 + b * NPT + pid;          // Fn [k2][b*32+p]
        d_Fnh[o] = hp; d_Fnl[o] = lp;
    } else {
        size_t o = ((size_t)b * 768 + k2) * NECOL + (pid - NPT);
        d_Eph[o] = hp; d_Epl[o] = lp;
    }
}

// ---------------- merged weight conversion ----------------
#define NWI (2 * 512 * 768)
#define NWC (2 * 512 * 256)
#define NWN (2048 * 768)
__global__ void convW(const float* __restrict__ g_iw, const float* __restrict__ p_iw,
                      const float* __restrict__ g_cw, const float* __restrict__ p_cw)
{
    int idx = blockIdx.x * 256 + threadIdx.x;
    if (idx < NWI) {
        int k2 = idx % 768;
        int r  = (idx / 768) & 511;
        int net = idx / (512 * 768);
        const float* w = (net ? p_iw : g_iw) + (size_t)r * 4608 + 3072 + 2 * k2;
        split_pair(w[0], w[1], d_WIh[idx], d_WIl[idx]);
    } else if (idx < NWI + NWC) {
        int q = idx - NWI;
        int k2 = q & 255;
        int r  = (q >> 8) & 511;
        int net = q >> 17;
        const float* w = (net ? p_cw : g_cw) + (size_t)r * 512 + 2 * k2;
        split_pair(w[0], w[1], d_CWh[q], d_CWl[q]);
    } else if (idx < NWI + NWC + NWN) {
        int q = idx - NWI - NWC;
        int k2 = q % 768;
        int r  = q / 768;
        int part = r >> 9;
        const float* w = (part >= 2 ? p_iw : g_iw) + (size_t)(r & 511) * 4608
                         + ((part & 1) ? 1536 : 0) + 2 * k2;
        split_pair(w[0], w[1], d_WNh[q], d_WNl[q]);
    }
}

// ---------------- convX: sum XcP halves -> full X (+Gi+Gj), BN/ReLU packed ----------------
__global__ void convX(const float* __restrict__ g_bg, const float* __restrict__ g_bb,
                      const float* __restrict__ g_bm, const float* __restrict__ g_bv,
                      const float* __restrict__ p_bg, const float* __restrict__ p_bb,
                      const float* __restrict__ p_bm, const float* __restrict__ p_bv)
{
    int idx = blockIdx.x * 256 + threadIdx.x;       // 8*2*256*1024
    int n  = idx & 1023;
    int t  = idx >> 10;
    int k2 = t & 255;
    int z  = t >> 8;
    int b = z >> 1, net = z & 1;
    int k = 2 * k2;

    int i = n >> 5, j = n & 31;
    int ii = min(i, j), jj = max(i, j);
    int c = pair_index(ii, jj);

    size_t crow = ((size_t)b * 1024 + net * 512 + k) * NECOL + c;
    float v0 = d_XcP[crow] + d_XcP[XC_HALF + crow];
    float v1 = d_XcP[crow + NECOL] + d_XcP[XC_HALF + crow + NECOL];

    size_t gi = ((size_t)b * 2048 + net * 1024 + k) * NPT;
    size_t gj = gi + (size_t)512 * NPT;
    float x0 = v0 + d_Gn[gi + i] + d_Gn[gj + j];
    float x1 = v1 + d_Gn[gi + NPT + i] + d_Gn[gj + NPT + j];

    size_t xrow = ((size_t)b * 1024 + net * 512 + k) * NEDGE + n;
    d_X[xrow] = x0;
    d_X[xrow + NEDGE] = x1;

    const float* BG = net ? p_bg : g_bg;
    const float* BB = net ? p_bb : g_bb;
    const float* BM = net ? p_bm : g_bm;
    const float* BV = net ? p_bv : g_bv;
    float sc0 = BG[k] * rsqrtf(BV[k] + 1e-5f);
    float sh0 = BB[k] - BM[k] * sc0;
    float sc1 = BG[k + 1] * rsqrtf(BV[k + 1] + 1e-5f);
    float sh1 = BB[k + 1] - BM[k + 1] * sc1;
    float y0 = fmaxf(x0 * sc0 + sh0, 0.f);
    float y1 = fmaxf(x1 * sc1 + sh1, 0.f);
    split_pair(y0, y1, d_Xph[idx], d_Xpl[idx]);
}

// ---------------- HMMA GEMM, cp.async double-buffered, ldmatrix A-frags ----------------
// MODE 0 (intro): compact store to d_XcP; K-split 2 via blockIdx.y LSB
// MODE 1 (chorus): Y = D + X + cb
// MODE 2 (node):   GnP partials (k-split 4 via blockIdx.z)
template<int K2TOT, int NTOT, int MODE>
__global__ void __launch_bounds__(256, 2) gemm_mma(
    const uint32_t* __restrict__ Ah_g, const uint32_t* __restrict__ Al_g,
    const uint32_t* __restrict__ Bh_g, const uint32_t* __restrict__ Bl_g,
    const float* __restrict__ g_cb, const float* __restrict__ p_cb)
{
    extern __shared__ uint32_t smw[];
    const uint32_t sbase = smem_u32(smw);

    const int tid  = threadIdx.x;
    const int lane = tid & 31, wid = tid >> 5;
    const int wm = wid >> 2, wn = wid & 3;
    const int b    = blockIdx.z;
    const int half = (MODE == 0) ? (blockIdx.y & 1) : 0;
    const int row0 = (MODE == 0) ? (blockIdx.y >> 1) * 128 : blockIdx.y * 128;
    const int col0 = blockIdx.x * 128;
    const int net  = (row0 >> 9) & 1;

    const uint32_t* Ah = Ah_g + (size_t)row0 * K2TOT;
    const uint32_t* Al = Al_g + (size_t)row0 * K2TOT;
    const int bz = (MODE == 0) ? b : (MODE == 1 ? b * 2 + net : 0);
    const uint32_t* Bh = Bh_g + (size_t)bz * K2TOT * NTOT + col0;
    const uint32_t* Bl = Bl_g + (size_t)bz * K2TOT * NTOT + col0;

    constexpr int NCH = K2TOT / 16;
    constexpr int CHUNKS = (MODE == 2) ? NCH / 4 : (MODE == 0 ? NCH / 2 : NCH);
    const int kc0 = (MODE == 2) ? blockIdx.z * CHUNKS : (MODE == 0 ? half * CHUNKS : 0);

    const int lrow = lane & 15;
    const int lcolw = (lane >> 4) * 4;

    #define PREFETCH(kc, bufw) do { \
        _Pragma("unroll") \
        for (int i = 0; i < 2; i++) { \
            int t = tid + i * 256; \
            int row = t >> 2, seg = t & 3; \
            size_t go = (size_t)row * K2TOT + (kc) * 16 + seg * 4; \
            cpa16(sbase + ((bufw) + AH_O + row * 20 + seg * 4) * 4, Ah + go); \
            cpa16(sbase + ((bufw) + AL_O + row * 20 + seg * 4) * 4, Al + go); \
            int brow = t >> 5, bseg = t & 31; \
            size_t gb = (size_t)((kc) * 16 + brow) * NTOT + bseg * 4; \
            cpa16(sbase + ((bufw) + BH_O + brow * 136 + bseg * 4) * 4, Bh + gb); \
            cpa16(sbase + ((bufw) + BL_O + brow * 136 + bseg * 4) * 4, Bl + gb); \
        } \
        asm volatile("cp.async.commit_group;" ::: "memory"); \
    } while (0)

    float acc[4][4][4];
    #pragma unroll
    for (int i = 0; i < 4; i++)
        #pragma unroll
        for (int j = 0; j < 4; j++)
            #pragma unroll
            for (int v = 0; v < 4; v++) acc[i][j][v] = 0.f;

    PREFETCH(kc0, 0);

    #pragma unroll 1
    for (int ci = 0; ci < CHUNKS; ci++) {
        const int bufw = (ci & 1) * BUF_WORDS;
        if (ci + 1 < CHUNKS) {
            PREFETCH(kc0 + ci + 1, ((ci + 1) & 1) * BUF_WORDS);
            asm volatile("cp.async.wait_group 1;" ::: "memory");
        } else {
            asm volatile("cp.async.wait_group 0;" ::: "memory");
        }
        __syncthreads();

        const uint32_t* BhS = smw + bufw + BH_O;
        const uint32_t* BlS = smw + bufw + BL_O;

        #pragma unroll
        for (int s = 0; s < 2; s++) {
            const int k2a = s * 8 + (lane & 3);
            uint32_t bh[4][2], bl[4][2];
            #pragma unroll
            for (int nf = 0; nf < 4; nf++) {
                int n = wn * 32 + nf * 8 + (lane >> 2);
                bh[nf][0] = BhS[k2a * 136 + n];
                bh[nf][1] = BhS[(k2a + 4) * 136 + n];
                bl[nf][0] = BlS[k2a * 136 + n];
                bl[nf][1] = BlS[(k2a + 4) * 136 + n];
            }
            #pragma unroll
            for (int mf = 0; mf < 4; mf++) {
                uint32_t aaddr = sbase + (uint32_t)((ci & 1) * BUF_WORDS + AH_O
                                 + (wm * 64 + mf * 16 + lrow) * 20 + s * 8 + lcolw) * 4;
                uint32_t ah[4], al[4];
                ldsm4(ah, aaddr);
                ldsm4(al, aaddr + A_WORDS * 4);
                #pragma unroll
                for (int nf = 0; nf < 4; nf++) {
                    mma16816(acc[mf][nf], ah, bh[nf]);
                    mma16816(acc[mf][nf], ah, bl[nf]);
                    mma16816(acc[mf][nf], al, bh[nf]);
                }
            }
        }
        __syncthreads();
    }
    #undef PREFETCH

    // ---- epilogue ----
    #pragma unroll
    for (int mf = 0; mf < 4; mf++) {
        int row_g = row0 + wm * 64 + mf * 16 + (lane >> 2);
        #pragma unroll
        for (int nf = 0; nf < 4; nf++) {
            int colg = col0 + wn * 32 + nf * 8 + (lane & 3) * 2;
            float* a = acc[mf][nf];
            if (MODE == 2) {
                int bb = colg >> 5, p = colg & 31;
                float* dst = d_GnP + (((size_t)blockIdx.z * 8 + bb) * 2048) * NPT;
                *(float2*)&dst[(size_t)row_g * NPT + p] = make_float2(a[0], a[1]);
                *(float2*)&dst[(size_t)(row_g + 8) * NPT + p] = make_float2(a[2], a[3]);
            } else if (MODE == 0) {
                float* dst = d_XcP + (size_t)half * XC_HALF;
                size_t obase = ((size_t)b * 1024 + row_g) * NECOL;
                *(float2*)&dst[obase + colg] = make_float2(a[0], a[1]);
                *(float2*)&dst[obase + 8 * NECOL + colg] = make_float2(a[2], a[3]);
            } else {
                size_t obase = ((size_t)b * 1024 + row_g) * NEDGE;
                int r = row_g & 511;
                const float* CB = net ? p_cb : g_cb;
                float cb0 = CB[r], cb8 = CB[r + 8];
                float2 x0 = *(const float2*)&d_X[obase + colg];
                float2 x1 = *(const float2*)&d_X[obase + 8 * NEDGE + colg];
                float2 w0 = make_float2(a[0] + x0.x + cb0, a[1] + x0.y + cb0);
                float2 w1 = make_float2(a[2] + x1.x + cb8, a[3] + x1.y + cb8);
                *(float2*)&d_Y[obase + colg] = w0;
                *(float2*)&d_Y[obase + 8 * NEDGE + colg] = w1;
            }
        }
    }
}

// ---------------- reduce node partials + bias ----------------
__global__ void reduceGn(const float* __restrict__ g_ib, const float* __restrict__ p_ib)
{
    int idx = blockIdx.x * 256 + threadIdx.x;
    int r = (idx >> 5) & 2047;
    float bias = (r < 512) ? g_ib[r] : ((r >= 1024 && r < 1536) ? p_ib[r - 1024] : 0.f);
    float s = bias;
    #pragma unroll
    for (int z = 0; z < 4; z++)
        s += d_GnP[(size_t)z * (8 * 2048 * NPT) + idx];
    d_Gn[idx] = s;
}

// ---------------- outro ----------------
__global__ void __launch_bounds__(128) outro_kernel(const float* __restrict__ g_ow,
                                                    const float* __restrict__ p_ow)
{
    __shared__ float wg[128];
    __shared__ float wp[64 * 128];
    const int tx = threadIdx.x;
    const int m  = blockIdx.x * 128 + tx;
    const int b  = blockIdx.y;
    const int rz = blockIdx.z;
    const int r0 = rz * 128;

    wg[tx] = g_ow[r0 + tx];
    for (int i = tx; i < 64 * 128; i += 128) {
        int oc = i >> 7, r = i & 127;
        wp[i] = p_ow[(size_t)oc * 512 + r0 + r];
    }
    __syncthreads();

    float accg = 0.f;
    float acc[64];
    #pragma unroll
    for (int oc = 0; oc < 64; oc++) acc[oc] = 0.f;

    const float* Yg = d_Y + ((size_t)b * 1024 + r0) * NEDGE + m;
    const float* Yp = Yg + (size_t)512 * NEDGE;
    #pragma unroll 4
    for (int r = 0; r < 128; r++) {
        float yg = Yg[(size_t)r * NEDGE];
        float yp = Yp[(size_t)r * NEDGE];
        accg += wg[r] * yg;
        #pragma unroll
        for (int oc = 0; oc < 64; oc++)
            acc[oc] += wp[oc * 128 + r] * yp;
    }

    d_gateP[((size_t)rz * 8 + b) * NEDGE + m] = accg;
    float* dst = d_prP + ((size_t)rz * 8 + b) * 64 * NEDGE + m;
    #pragma unroll
    for (int oc = 0; oc < 64; oc++)
        dst[(size_t)oc * NEDGE] = acc[oc];
}

// ---------------- final ----------------
__global__ void final_kernel(const int* __restrict__ nvec,
                             const float* __restrict__ g_ob, const float* __restrict__ p_ob,
                             float* __restrict__ out)
{
    const int m = blockIdx.x * blockDim.x + threadIdx.x;
    const int b = blockIdx.y;
    if (m >= NEDGE) return;
    const int i = m >> 5, j = m & 31;
    const int nb = nvec[b];
    const bool ok = (i < nb) && (j < nb);

    float gsum = g_ob[0];
    #pragma unroll
    for (int z = 0; z < 4; z++)
        gsum += d_gateP[((size_t)z * 8 + b) * NEDGE + m];

    float pv[64];
    float ss = 0.f;
    #pragma unroll
    for (int c = 0; c < 64; c++) {
        float v = p_ob[c];
        #pragma unroll
        for (int z = 0; z < 4; z++)
            v += d_prP[(((size_t)z * 8 + b) * 64 + c) * NEDGE + m];
        pv[c] = v;
        ss += v * v;
    }
    float g = 1.f / (1.f + expf(-gsum));
    float s = ok ? (g / fmaxf(sqrtf(ss), 1e-12f)) : 0.f;

    #pragma unroll
    for (int c = 0; c < 64; c++)
        out[((size_t)b * 64 + c) * NEDGE + m] = pv[c] * s;
}

// ---------------- launch ----------------
extern "C" void kernel_launch(void* const* d_in, const int* in_sizes, int n_in,
                              void* d_out, int out_size)
{
    const float* f0 = (const float*)d_in[0];
    const float* f1 = (const float*)d_in[1];
    const float* f2 = (const float*)d_in[2];
    const float* f3 = (const float*)d_in[3];
    const float* f4 = (const float*)d_in[4];
    const float* f5 = (const float*)d_in[5];
    const float* P  = (const float*)d_in[6];
    const int*   nv = (const int*)d_in[7];
    const float* g_iw = (const float*)d_in[8];
    const float* g_ib = (const float*)d_in[9];
    const float* g_bg = (const float*)d_in[10];
    const float* g_bb = (const float*)d_in[11];
    const float* g_bm = (const float*)d_in[12];
    const float* g_bv = (const float*)d_in[13];
    const float* g_cw = (const float*)d_in[14];
    const float* g_cb = (const float*)d_in[15];
    const float* g_ow = (const float*)d_in[16];
    const float* g_ob = (const float*)d_in[17];
    const float* p_iw = (const float*)d_in[18];
    const float* p_ib = (const float*)d_in[19];
    const float* p_bg = (const float*)d_in[20];
    const float* p_bb = (const float*)d_in[21];
    const float* p_bm = (const float*)d_in[22];
    const float* p_bv = (const float*)d_in[23];
    const float* p_cw = (const float*)d_in[24];
    const float* p_cb = (const float*)d_in[25];
    const float* p_ow = (const float*)d_in[26];
    const float* p_ob = (const float*)d_in[27];
    float* out = (float*)d_out;

    cudaFuncSetAttribute(gemm_mma<768, NECOL, 0>, cudaFuncAttributeMaxDynamicSharedMemorySize, GEMM_SMEM_BYTES);
    cudaFuncSetAttribute(gemm_mma<256, 1024, 1>,  cudaFuncAttributeMaxDynamicSharedMemorySize, GEMM_SMEM_BYTES);
    cudaFuncSetAttribute(gemm_mma<768, 256, 2>,   cudaFuncAttributeMaxDynamicSharedMemorySize, GEMM_SMEM_BYTES);

    uint32_t *pWIh, *pWIl, *pCWh, *pCWl, *pWNh, *pWNl, *pEph, *pEpl, *pFnh, *pFnl, *pXph, *pXpl;
    cudaGetSymbolAddress((void**)&pWIh, d_WIh);
    cudaGetSymbolAddress((void**)&pWIl, d_WIl);
    cudaGetSymbolAddress((void**)&pCWh, d_CWh);
    cudaGetSymbolAddress((void**)&pCWl, d_CWl);
    cudaGetSymbolAddress((void**)&pWNh, d_WNh);
    cudaGetSymbolAddress((void**)&pWNl, d_WNl);
    cudaGetSymbolAddress((void**)&pEph, d_Eph);
    cudaGetSymbolAddress((void**)&pEpl, d_Epl);
    cudaGetSymbolAddress((void**)&pFnh, d_Fnh);
    cudaGetSymbolAddress((void**)&pFnl, d_Fnl);
    cudaGetSymbolAddress((void**)&pXph, d_Xph);
    cudaGetSymbolAddress((void**)&pXpl, d_Xpl);

    alignPack<<<(BSZ * 768 * QTOT + 255) / 256, 256>>>(f0, f1, f2, f3, f4, f5, P);
    convW<<<(NWI + NWC + NWN + 255) / 256, 256>>>(g_iw, p_iw, g_cw, p_cw);

    // intro: K-split 2 (blockIdx.y = row_tile*2 + half), grid 640 CTAs
    gemm_mma<768, NECOL, 0><<<dim3(5, 16, BSZ), 256, GEMM_SMEM_BYTES>>>(
        pWIh, pWIl, pEph, pEpl, nullptr, nullptr);

    gemm_mma<768, 256, 2><<<dim3(2, 16, 4), 256, GEMM_SMEM_BYTES>>>(
        pWNh, pWNl, pFnh, pFnl, nullptr, nullptr);
    reduceGn<<<(BSZ * 2048 * NPT) / 256, 256>>>(g_ib, p_ib);

    convX<<<(BSZ * 2 * 256 * 1024) / 256, 256>>>(g_bg, g_bb, g_bm, g_bv,
                                                 p_bg, p_bb, p_bm, p_bv);

    gemm_mma<256, 1024, 1><<<dim3(8, 8, BSZ), 256, GEMM_SMEM_BYTES>>>(
        pCWh, pCWl, pXph, pXpl, g_cb, p_cb);

    outro_kernel<<<dim3(8, BSZ, 4), 128>>>(g_ow, p_ow);
    final_kernel<<<dim3(4, BSZ), 256>>>(nv, g_ob, p_ob, out);
}